// round 2
// baseline (speedup 1.0000x reference)
#include <cuda_runtime.h>
#include <cuda_bf16.h>

#define BB 64
#define NQ 300
#define TT 30
#define KSLOT 10            // ceil(300/32)
#define BIGF 1e18f

// per-batch partial sums: [B][3] = {bce_sum, l1_sum, giou_sum}
__device__ float g_partials[BB * 3];
__device__ unsigned g_count;   // zero-initialized; last block resets it each launch

__device__ __forceinline__ unsigned float_key(float f) {
    unsigned b = __float_as_uint(f);
    return (b & 0x80000000u) ? ~b : (b | 0x80000000u);
}
__device__ __forceinline__ float key_float(unsigned k) {
    return __uint_as_float((k & 0x80000000u) ? (k ^ 0x80000000u) : ~k);
}

__global__ __launch_bounds__(256)
void detr_criterion_kernel(const float* __restrict__ pred_boxes,
                           const float* __restrict__ pred_classes,
                           const float* __restrict__ targets,
                           float* __restrict__ out)
{
    __shared__ float cost[TT * NQ];     // [t][n]
    __shared__ float spc_sh[NQ];        // dumped once per row for dual-u update
    __shared__ int   path_sh[NQ];       // dumped once per row for augmentation
    __shared__ int   row4col[NQ];
    __shared__ unsigned char matched[NQ];
    __shared__ float u[TT];
    __shared__ unsigned char SR[TT];
    __shared__ int   col4row[TT];
    __shared__ int   sorted_idx[TT];
    __shared__ float warpsum[8];
    __shared__ float l1s[TT];
    __shared__ float gis[TT];
    __shared__ int   s_last;

    const int b   = blockIdx.x;
    const int tid = threadIdx.x;
    const float* pb = pred_boxes   + (size_t)b * NQ * 4;
    const float* pc = pred_classes + (size_t)b * NQ;
    const float* tg = targets      + (size_t)b * TT * 4;

    // ---- cost matrix: cost[t][n] = -pc[n] - giou(pred n, tgt t) + L1(pred n, tgt t)
    for (int idx = tid; idx < TT * NQ; idx += blockDim.x) {
        int t = idx / NQ, n = idx % NQ;
        float px = pb[n * 4 + 0], py = pb[n * 4 + 1];
        float pw = pb[n * 4 + 2], ph = pb[n * 4 + 3];
        float tx = tg[t * 4 + 0], ty = tg[t * 4 + 1];
        float tw = tg[t * 4 + 2], th = tg[t * 4 + 3];

        float ax0 = px, ay0 = py, ax1 = px + pw, ay1 = py + ph;
        float bx0 = tx, by0 = ty, bx1 = tx + tw, by1 = ty + th;

        float area_a = (ax1 - ax0) * (ay1 - ay0);
        float area_b = (bx1 - bx0) * (by1 - by0);
        float iw = fmaxf(fminf(ax1, bx1) - fmaxf(ax0, bx0), 0.0f);
        float ih = fmaxf(fminf(ay1, by1) - fmaxf(ay0, by0), 0.0f);
        float inter = iw * ih;
        float uni = area_a + area_b - inter;
        float iou = inter / uni;
        float cw = fmaxf(fmaxf(ax1, bx1) - fminf(ax0, bx0), 0.0f);
        float ch = fmaxf(fmaxf(ay1, by1) - fminf(ay0, by0), 0.0f);
        float areac = cw * ch;
        float giou = iou - (areac - uni) / areac;

        float l1 = fabsf(px - tx) + fabsf(py - ty) + fabsf(pw - tw) + fabsf(ph - th);
        cost[idx] = -pc[n] - giou + l1;
    }
    for (int j = tid; j < NQ; j += blockDim.x) { row4col[j] = -1; matched[j] = 0; }
    if (tid < TT) { u[tid] = 0.0f; SR[tid] = 0; col4row[tid] = -1; }
    __syncthreads();

    // ---- Hungarian (shortest augmenting path), warp 0, register-resident column state
    if (tid < 32) {
        const int lane = tid;
        const unsigned FULL = 0xffffffffu;
        const bool slot9 = (lane < NQ - 9 * 32);   // lane < 12

        float vv[KSLOT];                 // dual v, persists across rows
        float sp[KSLOT];                 // shortest path costs
        int   pth[KSLOT];                // predecessor row
        unsigned scmask = 0;             // SC bits for my 10 columns
        #pragma unroll
        for (int k = 0; k < KSLOT; ++k) { vv[k] = 0.0f; sp[k] = BIGF; pth[k] = 0; }

        for (int row = 0; row < TT; ++row) {
            int cur_i = row;
            float minVal = 0.0f;
            int sink = -1;

            while (sink < 0) {
                if (lane == 0) SR[cur_i] = 1;
                float c0 = minVal - u[cur_i];
                const float* crow = &cost[cur_i * NQ];

                float bestVal = BIGF;
                int   bestJ   = 0x7fffffff;
                #pragma unroll
                for (int k = 0; k < KSLOT; ++k) {
                    if (k < KSLOT - 1 || slot9) {
                        if (!((scmask >> k) & 1u)) {
                            float red = c0 + crow[k * 32 + lane] - vv[k];
                            if (red < sp[k]) { sp[k] = red; pth[k] = cur_i; }
                            // ascending k => ascending j: strict < keeps first index
                            if (sp[k] < bestVal) { bestVal = sp[k]; bestJ = k * 32 + lane; }
                        }
                    }
                }
                // argmin with first-index tie-break (matches jnp.argmin)
                unsigned kb   = float_key(bestVal);
                unsigned kmin = __reduce_min_sync(FULL, kb);
                unsigned jc   = (kb == kmin) ? (unsigned)bestJ : 0xffffffffu;
                unsigned jmin = __reduce_min_sync(FULL, jc);
                minVal = key_float(kmin);

                if ((int)(jmin & 31u) == lane) scmask |= 1u << (jmin >> 5);
                int r = row4col[jmin];            // stable during search; broadcast LDS
                if (r < 0) sink = (int)jmin; else cur_i = r;
            }

            // dump spc/path to shared for dual-u update and augmentation
            #pragma unroll
            for (int k = 0; k < KSLOT; ++k) {
                if (k < KSLOT - 1 || slot9) {
                    spc_sh[k * 32 + lane]  = sp[k];
                    path_sh[k * 32 + lane] = pth[k];
                }
            }
            __syncwarp();

            // dual updates (use pre-augmentation col4row)
            #pragma unroll
            for (int k = 0; k < KSLOT; ++k)
                if ((scmask >> k) & 1u) vv[k] -= (minVal - sp[k]);
            if (lane < TT) {
                if (lane == row) u[lane] += minVal;
                else if (SR[lane]) u[lane] += minVal - spc_sh[col4row[lane]];
            }
            __syncwarp();

            // augment along alternating path (serial, lane 0)
            if (lane == 0) {
                int j = sink;
                for (;;) {
                    int i = path_sh[j];
                    row4col[j] = i;
                    int nj = col4row[i];
                    col4row[i] = j;
                    if (i == row) break;
                    j = nj;
                }
            }
            __syncwarp();

            // reset per-row state
            scmask = 0;
            #pragma unroll
            for (int k = 0; k < KSLOT; ++k) { sp[k] = BIGF; pth[k] = 0; }
            if (lane < TT) SR[lane] = 0;
            __syncwarp();
        }

        // boxes_idx = sort(col4row); mark matched set
        if (lane == 0) {
            for (int i = 0; i < TT; ++i) sorted_idx[i] = col4row[i];
            for (int i = 1; i < TT; ++i) {
                int key = sorted_idx[i];
                int k = i - 1;
                while (k >= 0 && sorted_idx[k] > key) { sorted_idx[k + 1] = sorted_idx[k]; --k; }
                sorted_idx[k + 1] = key;
            }
            for (int i = 0; i < TT; ++i) matched[sorted_idx[i]] = 1;
        }
    }
    __syncthreads();

    // ---- BCE over all N queries
    float local = 0.0f;
    for (int n = tid; n < NQ; n += blockDim.x) {
        float p = pc[n];
        float lg = matched[n] ? logf(p) : logf(1.0f - p);
        local += -fmaxf(lg, -100.0f);
    }
    #pragma unroll
    for (int off = 16; off; off >>= 1)
        local += __shfl_down_sync(0xffffffffu, local, off);
    if ((tid & 31) == 0) warpsum[tid >> 5] = local;

    // ---- L1 + GIoU on matched (sorted-index) pairs
    if (tid < TT) {
        int t = tid;
        int n = sorted_idx[t];
        float px = pb[n * 4 + 0], py = pb[n * 4 + 1];
        float pw = pb[n * 4 + 2], ph = pb[n * 4 + 3];
        float tx = tg[t * 4 + 0], ty = tg[t * 4 + 1];
        float tw = tg[t * 4 + 2], th = tg[t * 4 + 3];
        l1s[t] = fabsf(px - tx) + fabsf(py - ty) + fabsf(pw - tw) + fabsf(ph - th);

        float ax0 = px, ay0 = py, ax1 = px + pw, ay1 = py + ph;
        float bx0 = tx, by0 = ty, bx1 = tx + tw, by1 = ty + th;
        float area_a = (ax1 - ax0) * (ay1 - ay0);
        float area_b = (bx1 - bx0) * (by1 - by0);
        float iw = fmaxf(fminf(ax1, bx1) - fmaxf(ax0, bx0), 0.0f);
        float ih = fmaxf(fminf(ay1, by1) - fmaxf(ay0, by0), 0.0f);
        float inter = iw * ih;
        float uni = area_a + area_b - inter;
        float iou = inter / uni;
        float cw = fmaxf(fmaxf(ax1, bx1) - fminf(ax0, bx0), 0.0f);
        float ch = fmaxf(fmaxf(ay1, by1) - fminf(ay0, by0), 0.0f);
        float areac = cw * ch;
        float giou = iou - (areac - uni) / areac;
        gis[t] = 1.0f - giou;
    }
    __syncthreads();

    // ---- per-batch partials + last-block final reduction (deterministic order)
    if (tid == 0) {
        float bce = 0.0f;
        #pragma unroll
        for (int w = 0; w < 8; ++w) bce += warpsum[w];
        float l1 = 0.0f, gi = 0.0f;
        for (int t = 0; t < TT; ++t) { l1 += l1s[t]; gi += gis[t]; }
        g_partials[b * 3 + 0] = bce;
        g_partials[b * 3 + 1] = l1;
        g_partials[b * 3 + 2] = gi;
        __threadfence();
        unsigned ticket = atomicAdd(&g_count, 1u);
        s_last = (ticket == BB - 1) ? 1 : 0;
    }
    __syncthreads();

    if (s_last) {
        __threadfence();   // all other blocks' partials are globally visible
        if (tid < 3) {
            float s = 0.0f;
            for (int bb2 = 0; bb2 < BB; ++bb2) s += g_partials[bb2 * 3 + tid];
            float denom = (tid == 0) ? (float)(BB * NQ) : (float)(BB * TT);
            out[tid] = s / denom;
        }
        if (tid == 0) g_count = 0;   // reset for next graph replay
    }
}

extern "C" void kernel_launch(void* const* d_in, const int* in_sizes, int n_in,
                              void* d_out, int out_size)
{
    const float* pred_boxes = nullptr;
    const float* pred_classes = nullptr;
    const float* targets = nullptr;
    for (int i = 0; i < n_in; ++i) {
        if (in_sizes[i] == BB * NQ * 4)      pred_boxes   = (const float*)d_in[i];
        else if (in_sizes[i] == BB * NQ)     pred_classes = (const float*)d_in[i];
        else if (in_sizes[i] == BB * TT * 4) targets      = (const float*)d_in[i];
    }
    detr_criterion_kernel<<<BB, 256>>>(pred_boxes, pred_classes, targets, (float*)d_out);
}

// round 4
// speedup vs baseline: 1.2541x; 1.2541x over previous
#include <cuda_runtime.h>
#include <cuda_bf16.h>

#define BB 64
#define NQ 300
#define TT 30
#define BIGF 1e18f

// per-batch partial sums: [B][3] = {bce_sum, l1_sum, giou_sum}
__device__ float g_partials[BB * 3];
__device__ unsigned g_count;   // zero-init; last block resets each launch (graph-replay safe)

__device__ __forceinline__ unsigned float_key(float f) {
    unsigned b = __float_as_uint(f);
    return (b & 0x80000000u) ? ~b : (b | 0x80000000u);
}
__device__ __forceinline__ float key_float(unsigned k) {   // exact inverse of float_key
    return __uint_as_float((k & 0x80000000u) ? (k ^ 0x80000000u) : ~k);
}

__global__ __launch_bounds__(256)
void detr_criterion_kernel(const float* __restrict__ pred_boxes,
                           const float* __restrict__ pred_classes,
                           const float* __restrict__ targets,
                           float* __restrict__ out)
{
    __shared__ float cost[TT * NQ];     // [t][n]
    __shared__ float spc[NQ];
    __shared__ float v[NQ];
    __shared__ int   path[NQ];
    __shared__ int   row4col[NQ];
    __shared__ unsigned char SC[NQ];
    __shared__ unsigned char matched[NQ];
    __shared__ float u[TT];
    __shared__ int   col4row[TT];
    __shared__ int   sorted_idx[TT];
    __shared__ float warpsum[8];
    __shared__ float l1s[TT];
    __shared__ float gis[TT];
    __shared__ int   s_last;

    const int b   = blockIdx.x;
    const int tid = threadIdx.x;
    const float* pb = pred_boxes   + (size_t)b * NQ * 4;
    const float* pc = pred_classes + (size_t)b * NQ;
    const float* tg = targets      + (size_t)b * TT * 4;

    // ---- cost matrix: cost[t][n] = -pc[n] - giou(pred n, tgt t) + L1(pred n, tgt t)
    for (int idx = tid; idx < TT * NQ; idx += blockDim.x) {
        int t = idx / NQ, n = idx % NQ;
        float px = pb[n * 4 + 0], py = pb[n * 4 + 1];
        float pw = pb[n * 4 + 2], ph = pb[n * 4 + 3];
        float tx = tg[t * 4 + 0], ty = tg[t * 4 + 1];
        float tw = tg[t * 4 + 2], th = tg[t * 4 + 3];

        float ax0 = px, ay0 = py, ax1 = px + pw, ay1 = py + ph;
        float bx0 = tx, by0 = ty, bx1 = tx + tw, by1 = ty + th;

        float area_a = (ax1 - ax0) * (ay1 - ay0);
        float area_b = (bx1 - bx0) * (by1 - by0);
        float iw = fmaxf(fminf(ax1, bx1) - fmaxf(ax0, bx0), 0.0f);
        float ih = fmaxf(fminf(ay1, by1) - fmaxf(ay0, by0), 0.0f);
        float inter = iw * ih;
        float uni = area_a + area_b - inter;
        float iou = inter / uni;
        float cw = fmaxf(fmaxf(ax1, bx1) - fminf(ax0, bx0), 0.0f);
        float ch = fmaxf(fmaxf(ay1, by1) - fminf(ay0, by0), 0.0f);
        float areac = cw * ch;
        float giou = iou - (areac - uni) / areac;

        float l1 = fabsf(px - tx) + fabsf(py - ty) + fabsf(pw - tw) + fabsf(ph - th);
        cost[idx] = -pc[n] - giou + l1;
    }
    for (int j = tid; j < NQ; j += blockDim.x) {
        v[j] = 0.0f; row4col[j] = -1; spc[j] = BIGF; SC[j] = 0; path[j] = 0; matched[j] = 0;
    }
    if (tid < TT) { u[tid] = 0.0f; col4row[tid] = -1; }
    __syncthreads();

    // ---- Hungarian (shortest augmenting path), warp 0 only, warp-synchronous
    if (tid < 32) {
        const int lane = tid;
        const unsigned FULL = 0xffffffffu;
        for (int row = 0; row < TT; ++row) {
            int cur_i = row;
            float minVal = 0.0f;
            int sink = -1;
            unsigned SRmask = 0;   // replicated register bitmask of visited rows

            while (sink < 0) {
                SRmask |= 1u << cur_i;
                float u_cur = u[cur_i];
                const float* crow = &cost[cur_i * NQ];

                float bestVal = BIGF;
                int   bestJ   = 0x7fffffff;
                #pragma unroll
                for (int k = 0; k < 10; ++k) {
                    int j = k * 32 + lane;
                    if (k < 9 || j < NQ) {
                        if (!SC[j]) {
                            // EXACT reference rounding order: ((minVal + c) - u) - v
                            float red = ((minVal + crow[j]) - u_cur) - v[j];
                            float s = spc[j];
                            if (red < s) { s = red; spc[j] = red; path[j] = cur_i; }
                            if (s < bestVal) { bestVal = s; bestJ = j; } // ascending j: first index kept
                        }
                    }
                }
                // argmin with first-index tie-break (matches jnp.argmin)
                unsigned kb   = float_key(bestVal);
                unsigned kmin = __reduce_min_sync(FULL, kb);
                unsigned jc   = (kb == kmin) ? (unsigned)bestJ : 0xffffffffu;
                unsigned jmin = __reduce_min_sync(FULL, jc);
                minVal = key_float(kmin);           // exact bit round-trip

                SC[jmin] = 1;                        // all lanes, same byte: self-ordered
                int r = row4col[jmin];               // read-only during search (broadcast)
                if (r < 0) sink = (int)jmin; else cur_i = r;
            }

            // ---- dual updates (use spc & pre-augmentation col4row)
            #pragma unroll
            for (int k = 0; k < 10; ++k) {
                int j = k * 32 + lane;
                if ((k < 9 || j < NQ) && SC[j]) v[j] -= (minVal - spc[j]);
            }
            if (lane < TT) {
                if (lane == row) u[lane] += minVal;
                else if ((SRmask >> lane) & 1u) u[lane] += minVal - spc[col4row[lane]];
            }
            __syncwarp();

            // ---- augment along alternating path (serial, lane 0)
            if (lane == 0) {
                int j = sink;
                for (;;) {
                    int i = path[j];
                    row4col[j] = i;
                    int nj = col4row[i];
                    col4row[i] = j;
                    if (i == row) break;
                    j = nj;
                }
            }
            __syncwarp();

            // ---- reset per-row state (owner lanes only -> self-consistent)
            #pragma unroll
            for (int k = 0; k < 10; ++k) {
                int j = k * 32 + lane;
                if (k < 9 || j < NQ) { spc[j] = BIGF; SC[j] = 0; }
            }
            __syncwarp();
        }

        // boxes_idx = sort(col4row); mark matched set
        if (lane == 0) {
            for (int i = 0; i < TT; ++i) sorted_idx[i] = col4row[i];
            for (int i = 1; i < TT; ++i) {
                int key = sorted_idx[i];
                int k = i - 1;
                while (k >= 0 && sorted_idx[k] > key) { sorted_idx[k + 1] = sorted_idx[k]; --k; }
                sorted_idx[k + 1] = key;
            }
            for (int i = 0; i < TT; ++i) matched[sorted_idx[i]] = 1;
        }
    }
    __syncthreads();

    // ---- BCE over all N queries
    float local = 0.0f;
    for (int n = tid; n < NQ; n += blockDim.x) {
        float p = pc[n];
        float lg = matched[n] ? logf(p) : logf(1.0f - p);
        local += -fmaxf(lg, -100.0f);
    }
    #pragma unroll
    for (int off = 16; off; off >>= 1)
        local += __shfl_down_sync(0xffffffffu, local, off);
    if ((tid & 31) == 0) warpsum[tid >> 5] = local;

    // ---- L1 + GIoU on matched (sorted-index) pairs
    if (tid < TT) {
        int t = tid;
        int n = sorted_idx[t];
        float px = pb[n * 4 + 0], py = pb[n * 4 + 1];
        float pw = pb[n * 4 + 2], ph = pb[n * 4 + 3];
        float tx = tg[t * 4 + 0], ty = tg[t * 4 + 1];
        float tw = tg[t * 4 + 2], th = tg[t * 4 + 3];
        l1s[t] = fabsf(px - tx) + fabsf(py - ty) + fabsf(pw - tw) + fabsf(ph - th);

        float ax0 = px, ay0 = py, ax1 = px + pw, ay1 = py + ph;
        float bx0 = tx, by0 = ty, bx1 = tx + tw, by1 = ty + th;
        float area_a = (ax1 - ax0) * (ay1 - ay0);
        float area_b = (bx1 - bx0) * (by1 - by0);
        float iw = fmaxf(fminf(ax1, bx1) - fmaxf(ax0, bx0), 0.0f);
        float ih = fmaxf(fminf(ay1, by1) - fmaxf(ay0, by0), 0.0f);
        float inter = iw * ih;
        float uni = area_a + area_b - inter;
        float iou = inter / uni;
        float cw = fmaxf(fmaxf(ax1, bx1) - fminf(ax0, bx0), 0.0f);
        float ch = fmaxf(fmaxf(ay1, by1) - fminf(ay0, by0), 0.0f);
        float areac = cw * ch;
        float giou = iou - (areac - uni) / areac;
        gis[t] = 1.0f - giou;
    }
    __syncthreads();

    // ---- per-batch partials + last-block final reduction (deterministic order)
    if (tid == 0) {
        float bce = 0.0f;
        #pragma unroll
        for (int w = 0; w < 8; ++w) bce += warpsum[w];
        float l1 = 0.0f, gi = 0.0f;
        for (int t = 0; t < TT; ++t) { l1 += l1s[t]; gi += gis[t]; }
        g_partials[b * 3 + 0] = bce;
        g_partials[b * 3 + 1] = l1;
        g_partials[b * 3 + 2] = gi;
        __threadfence();
        unsigned ticket = atomicAdd(&g_count, 1u);
        s_last = (ticket == BB - 1) ? 1 : 0;
    }
    __syncthreads();

    if (s_last) {
        __threadfence();   // all other blocks' partials globally visible
        if (tid < 3) {
            float s = 0.0f;
            for (int bb2 = 0; bb2 < BB; ++bb2) s += g_partials[bb2 * 3 + tid];
            float denom = (tid == 0) ? (float)(BB * NQ) : (float)(BB * TT);
            out[tid] = s / denom;
        }
        if (tid == 0) g_count = 0;   // reset for next graph replay
    }
}

extern "C" void kernel_launch(void* const* d_in, const int* in_sizes, int n_in,
                              void* d_out, int out_size)
{
    const float* pred_boxes = nullptr;
    const float* pred_classes = nullptr;
    const float* targets = nullptr;
    for (int i = 0; i < n_in; ++i) {
        if (in_sizes[i] == BB * NQ * 4)      pred_boxes   = (const float*)d_in[i];
        else if (in_sizes[i] == BB * NQ)     pred_classes = (const float*)d_in[i];
        else if (in_sizes[i] == BB * TT * 4) targets      = (const float*)d_in[i];
    }
    detr_criterion_kernel<<<BB, 256>>>(pred_boxes, pred_classes, targets, (float*)d_out);
}

// round 5
// speedup vs baseline: 1.2581x; 1.0032x over previous
#include <cuda_runtime.h>
#include <cuda_bf16.h>

#define BB 64
#define NQ 300
#define TT 30
#define BIGF 1e18f

// per-batch partial sums: [B][3] = {bce_sum, l1_sum, giou_sum}
__device__ float g_partials[BB * 3];
__device__ unsigned g_count;   // zero-init; last block resets each launch (graph-replay safe)

// order-isomorphic float <-> u32 key (exact round-trip)
__device__ __forceinline__ unsigned fkey(float f) {
    unsigned b = __float_as_uint(f);
    return b ^ (((unsigned)((int)b >> 31)) | 0x80000000u);
}
__device__ __forceinline__ float funkey(unsigned k) {
    unsigned m = ((unsigned)((int)(~k) >> 31)) | 0x80000000u;
    return __uint_as_float(k ^ m);
}

__global__ __launch_bounds__(256)
void detr_criterion_kernel(const float* __restrict__ pred_boxes,
                           const float* __restrict__ pred_classes,
                           const float* __restrict__ targets,
                           float* __restrict__ out)
{
    __shared__ float cost[TT * NQ];     // [t][n]
    __shared__ float spc_sh[NQ];        // mirror of spc (written on update only)
    __shared__ int   path_sh[NQ];       // mirror of path (written on update only)
    __shared__ int2  combo[NQ];         // {row4col[j], bits(u[row4col[j]])}, rebuilt per row
    __shared__ int   row4col[NQ];
    __shared__ unsigned char matched[NQ];
    __shared__ float u[TT];
    __shared__ int   col4row[TT];
    __shared__ int   sorted_idx[TT];
    __shared__ float warpsum[8];
    __shared__ float l1s[TT];
    __shared__ float gis[TT];
    __shared__ int   s_last;

    const int b   = blockIdx.x;
    const int tid = threadIdx.x;
    const float* pb = pred_boxes   + (size_t)b * NQ * 4;
    const float* pc = pred_classes + (size_t)b * NQ;
    const float* tg = targets      + (size_t)b * TT * 4;

    // ---- cost matrix: cost[t][n] = -pc[n] - giou(pred n, tgt t) + L1(pred n, tgt t)
    for (int idx = tid; idx < TT * NQ; idx += blockDim.x) {
        int t = idx / NQ, n = idx % NQ;
        float px = pb[n * 4 + 0], py = pb[n * 4 + 1];
        float pw = pb[n * 4 + 2], ph = pb[n * 4 + 3];
        float tx = tg[t * 4 + 0], ty = tg[t * 4 + 1];
        float tw = tg[t * 4 + 2], th = tg[t * 4 + 3];

        float ax0 = px, ay0 = py, ax1 = px + pw, ay1 = py + ph;
        float bx0 = tx, by0 = ty, bx1 = tx + tw, by1 = ty + th;

        float area_a = (ax1 - ax0) * (ay1 - ay0);
        float area_b = (bx1 - bx0) * (by1 - by0);
        float iw = fmaxf(fminf(ax1, bx1) - fmaxf(ax0, bx0), 0.0f);
        float ih = fmaxf(fminf(ay1, by1) - fmaxf(ay0, by0), 0.0f);
        float inter = iw * ih;
        float uni = area_a + area_b - inter;
        float iou = inter / uni;
        float cw = fmaxf(fmaxf(ax1, bx1) - fminf(ax0, bx0), 0.0f);
        float ch = fmaxf(fmaxf(ay1, by1) - fminf(ay0, by0), 0.0f);
        float areac = cw * ch;
        float giou = iou - (areac - uni) / areac;

        float l1 = fabsf(px - tx) + fabsf(py - ty) + fabsf(pw - tw) + fabsf(ph - th);
        cost[idx] = -pc[n] - giou + l1;
    }
    for (int j = tid; j < NQ; j += blockDim.x) { row4col[j] = -1; matched[j] = 0; }
    if (tid < TT) { u[tid] = 0.0f; col4row[tid] = -1; }
    __syncthreads();

    // ---- Hungarian (shortest augmenting path), warp 0 only, warp-synchronous
    if (tid < 32) {
        const int lane = tid;
        const unsigned FULL = 0xffffffffu;
        const unsigned scinit = (lane < NQ - 9 * 32) ? 0u : (1u << 9);  // lane>=12: slot 9 invalid
        const unsigned KBIG = fkey(BIGF);

        float vv[10];                 // dual v (register-resident, exact)
        #pragma unroll
        for (int k = 0; k < 10; ++k) vv[k] = 0.0f;

        for (int row = 0; row < TT; ++row) {
            // precompute combo[j] = {r, bits(u[r])}; u & row4col are static during a search
            #pragma unroll
            for (int k = 0; k < 10; ++k) {
                int j = k * 32 + lane;
                if (k < 9 || j < NQ) {
                    int r = row4col[j];
                    int ub = (r >= 0) ? __float_as_int(u[r]) : 0;
                    combo[j] = make_int2(r, ub);
                }
            }
            unsigned spkey[10];       // spc as order-isomorphic keys
            #pragma unroll
            for (int k = 0; k < 10; ++k) spkey[k] = KBIG;
            unsigned scmask = scinit;
            unsigned SRmask = 0;
            int   cur_i  = row;
            float u_cur  = u[row];
            float minVal = 0.0f;
            int   sink   = -1;
            __syncwarp();             // combo visible warp-wide

            while (sink < 0) {
                SRmask |= 1u << cur_i;
                const float* crow = &cost[cur_i * NQ];

                unsigned bestKey = 0xffffffffu;
                int      bestJ   = 0x7fffffff;
                #pragma unroll
                for (int k = 0; k < 10; ++k) {
                    int j = k * 32 + lane;
                    float c = crow[(k < 9) ? j : ((lane < NQ - 9 * 32) ? j : 0)];
                    // EXACT reference rounding order: ((minVal + c) - u) - v
                    float red = ((minVal + c) - u_cur) - vv[k];
                    unsigned kr = fkey(red);
                    bool sc  = (scmask >> k) & 1u;
                    bool upd = (!sc) && (kr < spkey[k]);       // unsigned cmp == float cmp
                    if (upd) { spkey[k] = kr; spc_sh[j] = red; path_sh[j] = cur_i; }
                    unsigned cand = sc ? 0xffffffffu : spkey[k];
                    if (cand < bestKey) { bestKey = cand; bestJ = j; } // ascending j: first index
                }
                unsigned kmin = __reduce_min_sync(FULL, bestKey);
                unsigned jc   = (bestKey == kmin) ? (unsigned)bestJ : 0xffffffffu;
                unsigned jmin = __reduce_min_sync(FULL, jc);
                minVal = funkey(kmin);                          // exact bit round-trip

                if ((int)(jmin & 31u) == lane) scmask |= 1u << (jmin >> 5);
                int2 cb = combo[jmin];                          // one LDS.64: {r, u[r]}
                if (cb.x < 0) sink = (int)jmin;
                else { cur_i = cb.x; u_cur = __int_as_float(cb.y); }
            }

            // ---- dual updates (exclude invalid-slot sentinel bits)
            unsigned scupd = scmask & ~scinit;
            #pragma unroll
            for (int k = 0; k < 10; ++k)
                if ((scupd >> k) & 1u) vv[k] -= (minVal - funkey(spkey[k]));
            __syncwarp();             // spc_sh / path_sh stores visible
            if (lane < TT) {
                if (lane == row) u[lane] += minVal;
                else if ((SRmask >> lane) & 1u) u[lane] += minVal - spc_sh[col4row[lane]];
            }
            __syncwarp();

            // ---- augment along alternating path (serial, lane 0)
            if (lane == 0) {
                int j = sink;
                for (;;) {
                    int i = path_sh[j];
                    row4col[j] = i;
                    int nj = col4row[i];
                    col4row[i] = j;
                    if (i == row) break;
                    j = nj;
                }
            }
            __syncwarp();
        }

        // boxes_idx = sort(col4row); mark matched set
        if (lane == 0) {
            for (int i = 0; i < TT; ++i) sorted_idx[i] = col4row[i];
            for (int i = 1; i < TT; ++i) {
                int key = sorted_idx[i];
                int k = i - 1;
                while (k >= 0 && sorted_idx[k] > key) { sorted_idx[k + 1] = sorted_idx[k]; --k; }
                sorted_idx[k + 1] = key;
            }
            for (int i = 0; i < TT; ++i) matched[sorted_idx[i]] = 1;
        }
    }
    __syncthreads();

    // ---- BCE over all N queries
    float local = 0.0f;
    for (int n = tid; n < NQ; n += blockDim.x) {
        float p = pc[n];
        float lg = matched[n] ? logf(p) : logf(1.0f - p);
        local += -fmaxf(lg, -100.0f);
    }
    #pragma unroll
    for (int off = 16; off; off >>= 1)
        local += __shfl_down_sync(0xffffffffu, local, off);
    if ((tid & 31) == 0) warpsum[tid >> 5] = local;

    // ---- L1 + GIoU on matched (sorted-index) pairs
    if (tid < TT) {
        int t = tid;
        int n = sorted_idx[t];
        float px = pb[n * 4 + 0], py = pb[n * 4 + 1];
        float pw = pb[n * 4 + 2], ph = pb[n * 4 + 3];
        float tx = tg[t * 4 + 0], ty = tg[t * 4 + 1];
        float tw = tg[t * 4 + 2], th = tg[t * 4 + 3];
        l1s[t] = fabsf(px - tx) + fabsf(py - ty) + fabsf(pw - tw) + fabsf(ph - th);

        float ax0 = px, ay0 = py, ax1 = px + pw, ay1 = py + ph;
        float bx0 = tx, by0 = ty, bx1 = tx + tw, by1 = ty + th;
        float area_a = (ax1 - ax0) * (ay1 - ay0);
        float area_b = (bx1 - bx0) * (by1 - by0);
        float iw = fmaxf(fminf(ax1, bx1) - fmaxf(ax0, bx0), 0.0f);
        float ih = fmaxf(fminf(ay1, by1) - fmaxf(ay0, by0), 0.0f);
        float inter = iw * ih;
        float uni = area_a + area_b - inter;
        float iou = inter / uni;
        float cw = fmaxf(fmaxf(ax1, bx1) - fminf(ax0, bx0), 0.0f);
        float ch = fmaxf(fmaxf(ay1, by1) - fminf(ay0, by0), 0.0f);
        float areac = cw * ch;
        float giou = iou - (areac - uni) / areac;
        gis[t] = 1.0f - giou;
    }
    __syncthreads();

    // ---- per-batch partials + last-block final reduction (deterministic order)
    if (tid == 0) {
        float bce = 0.0f;
        #pragma unroll
        for (int w = 0; w < 8; ++w) bce += warpsum[w];
        float l1 = 0.0f, gi = 0.0f;
        for (int t = 0; t < TT; ++t) { l1 += l1s[t]; gi += gis[t]; }
        g_partials[b * 3 + 0] = bce;
        g_partials[b * 3 + 1] = l1;
        g_partials[b * 3 + 2] = gi;
        __threadfence();
        unsigned ticket = atomicAdd(&g_count, 1u);
        s_last = (ticket == BB - 1) ? 1 : 0;
    }
    __syncthreads();

    if (s_last) {
        __threadfence();   // all other blocks' partials globally visible
        if (tid < 3) {
            float s = 0.0f;
            for (int bb2 = 0; bb2 < BB; ++bb2) s += g_partials[bb2 * 3 + tid];
            float denom = (tid == 0) ? (float)(BB * NQ) : (float)(BB * TT);
            out[tid] = s / denom;
        }
        if (tid == 0) g_count = 0;   // reset for next graph replay
    }
}

extern "C" void kernel_launch(void* const* d_in, const int* in_sizes, int n_in,
                              void* d_out, int out_size)
{
    const float* pred_boxes = nullptr;
    const float* pred_classes = nullptr;
    const float* targets = nullptr;
    for (int i = 0; i < n_in; ++i) {
        if (in_sizes[i] == BB * NQ * 4)      pred_boxes   = (const float*)d_in[i];
        else if (in_sizes[i] == BB * NQ)     pred_classes = (const float*)d_in[i];
        else if (in_sizes[i] == BB * TT * 4) targets      = (const float*)d_in[i];
    }
    detr_criterion_kernel<<<BB, 256>>>(pred_boxes, pred_classes, targets, (float*)d_out);
}

// round 6
// speedup vs baseline: 1.3693x; 1.0884x over previous
#include <cuda_runtime.h>
#include <cuda_bf16.h>

#define BB 64
#define NQ 300
#define NP 320            // padded column stride (k=0..4, 64 cols each)
#define TT 30
#define BIGF  1e18f
#define HUGEF 1e30f

// per-batch partial sums: [B][3] = {bce_sum, l1_sum, giou_sum}
__device__ float g_partials[BB * 3];
__device__ unsigned g_count;   // zero-init; last block resets each launch

// order-isomorphic float <-> u32 key (exact round-trip)
__device__ __forceinline__ unsigned fkey(float f) {
    unsigned b = __float_as_uint(f);
    return b ^ (((unsigned)((int)b >> 31)) | 0x80000000u);
}
__device__ __forceinline__ float funkey(unsigned k) {
    unsigned m = ((unsigned)((int)(~k) >> 31)) | 0x80000000u;
    return __uint_as_float(k ^ m);
}
__device__ __forceinline__ unsigned long long pack2(float x, float y) {
    unsigned long long r; asm("mov.b64 %0,{%1,%2};" : "=l"(r) : "f"(x), "f"(y)); return r;
}
__device__ __forceinline__ void unpack2(unsigned long long v, float& x, float& y) {
    asm("mov.b64 {%0,%1},%2;" : "=f"(x), "=f"(y) : "l"(v));
}
// two independent round-to-nearest f32 adds in one instruction (bit-exact per lane)
__device__ __forceinline__ unsigned long long add2(unsigned long long a, unsigned long long b) {
    unsigned long long r; asm("add.rn.f32x2 %0,%1,%2;" : "=l"(r) : "l"(a), "l"(b)); return r;
}

__global__ __launch_bounds__(256)
void detr_criterion_kernel(const float* __restrict__ pred_boxes,
                           const float* __restrict__ pred_classes,
                           const float* __restrict__ targets,
                           float* __restrict__ out)
{
    __shared__ float cost[TT * NP];     // [t][n], padded cols zeroed
    __shared__ float vneg[NP];          // -v[j]; pads = +1e30 (mask)
    __shared__ float spcfro[NP];        // frozen spc at selection (= minVal then)
    __shared__ int   path_sh[NP];
    __shared__ int2  combo[NQ];         // {row4col[j], bits(u[row4col[j]])}
    __shared__ int   row4col[NQ];
    __shared__ unsigned char matched[NQ];
    __shared__ float u[TT];
    __shared__ int   col4row[TT];
    __shared__ int   sorted_idx[TT];
    __shared__ float warpsum[8];
    __shared__ float l1s[TT];
    __shared__ float gis[TT];
    __shared__ int   s_last;

    const int b   = blockIdx.x;
    const int tid = threadIdx.x;
    const float* pb = pred_boxes   + (size_t)b * NQ * 4;
    const float* pc = pred_classes + (size_t)b * NQ;
    const float* tg = targets      + (size_t)b * TT * 4;

    // ---- cost matrix (padded): cost[t][n] = -pc[n] - giou + L1
    for (int idx = tid; idx < TT * NP; idx += blockDim.x) {
        int t = idx / NP, n = idx % NP;
        float cv = 0.0f;
        if (n < NQ) {
            float px = pb[n * 4 + 0], py = pb[n * 4 + 1];
            float pw = pb[n * 4 + 2], ph = pb[n * 4 + 3];
            float tx = tg[t * 4 + 0], ty = tg[t * 4 + 1];
            float tw = tg[t * 4 + 2], th = tg[t * 4 + 3];
            float ax0 = px, ay0 = py, ax1 = px + pw, ay1 = py + ph;
            float bx0 = tx, by0 = ty, bx1 = tx + tw, by1 = ty + th;
            float area_a = (ax1 - ax0) * (ay1 - ay0);
            float area_b = (bx1 - bx0) * (by1 - by0);
            float iw = fmaxf(fminf(ax1, bx1) - fmaxf(ax0, bx0), 0.0f);
            float ih = fmaxf(fminf(ay1, by1) - fmaxf(ay0, by0), 0.0f);
            float inter = iw * ih;
            float uni = area_a + area_b - inter;
            float iou = inter / uni;
            float cw = fmaxf(fmaxf(ax1, bx1) - fminf(ax0, bx0), 0.0f);
            float ch = fmaxf(fmaxf(ay1, by1) - fminf(ay0, by0), 0.0f);
            float areac = cw * ch;
            float giou = iou - (areac - uni) / areac;
            float l1 = fabsf(px - tx) + fabsf(py - ty) + fabsf(pw - tw) + fabsf(ph - th);
            cv = -pc[n] - giou + l1;
        }
        cost[idx] = cv;
    }
    for (int j = tid; j < NP; j += blockDim.x) vneg[j] = (j < NQ) ? 0.0f : HUGEF;
    for (int j = tid; j < NQ; j += blockDim.x) { row4col[j] = -1; matched[j] = 0; }
    if (tid < TT) { u[tid] = 0.0f; col4row[tid] = -1; }
    __syncthreads();

    // ---- Hungarian (shortest augmenting path), warp 0, warp-synchronous
    if (tid < 32) {
        const int lane = tid;
        const unsigned FULL = 0xffffffffu;
        const int lane2 = 2 * lane;

        for (int row = 0; row < TT; ++row) {
            // per-search state refresh
            float av[10];    // vneg per column; +1e30 once column enters SC (mask)
            float msp[10];   // masked spc (BIG when SC'd / never improved)
            #pragma unroll
            for (int k = 0; k < 5; ++k) {
                float2 vn = *(const float2*)&vneg[64 * k + lane2];
                av[2 * k] = vn.x; av[2 * k + 1] = vn.y;
                msp[2 * k] = BIGF; msp[2 * k + 1] = BIGF;
            }
            // combo[j] = {r, bits(u[r])}; static during a search
            for (int p = lane; p < NQ; p += 32) {
                int r = row4col[p];
                combo[p] = make_int2(r, (r >= 0) ? __float_as_int(u[r]) : 0);
            }
            unsigned SRmask = 0;
            int   cur_i  = row;
            float u_cur  = u[row];
            float minVal = 0.0f;
            int   sink   = -1;
            __syncwarp();

            while (sink < 0) {
                SRmask |= 1u << cur_i;
                const float2* crow2 = (const float2*)&cost[cur_i * NP];
                unsigned long long mv2 = pack2(minVal, minVal);
                unsigned long long nu2 = pack2(-u_cur, -u_cur);

                float bestVal = BIGF;
                int   bestJ   = 0x7fffffff;
                #pragma unroll
                for (int k = 0; k < 5; ++k) {
                    float2 c2 = crow2[k * 32 + lane];
                    // EXACT ref rounding: ((minVal + c) - u) - v  (sub == add of exact negation)
                    unsigned long long r2 = add2(add2(add2(pack2(c2.x, c2.y), mv2), nu2),
                                                 pack2(av[2 * k], av[2 * k + 1]));
                    float rx, ry; unpack2(r2, rx, ry);
                    int j0 = 64 * k + lane2;
                    if (rx < msp[2 * k])     { msp[2 * k] = rx;     path_sh[j0] = cur_i; }
                    if (msp[2 * k] < bestVal)     { bestVal = msp[2 * k];     bestJ = j0; }
                    if (ry < msp[2 * k + 1]) { msp[2 * k + 1] = ry; path_sh[j0 + 1] = cur_i; }
                    if (msp[2 * k + 1] < bestVal) { bestVal = msp[2 * k + 1]; bestJ = j0 + 1; }
                }
                // global argmin, first-index tie-break (jnp.argmin semantics)
                unsigned kb   = fkey(bestVal);
                unsigned kmin = __reduce_min_sync(FULL, kb);
                unsigned jc   = (kb == kmin) ? (unsigned)bestJ : 0xffffffffu;
                unsigned jmin = __reduce_min_sync(FULL, jc);
                minVal = funkey(kmin);                 // exact round-trip

                if (lane == 0) spcfro[jmin] = minVal;  // frozen spc value of SC'd column
                // freeze column jmin: mask from argmin + make future reds huge
                bool own = (lane == (int)((jmin & 63u) >> 1));
                int  slot = (int)(((jmin >> 6) << 1) | (jmin & 1u));
                #pragma unroll
                for (int s = 0; s < 10; ++s)
                    if (own && slot == s) { msp[s] = BIGF; av[s] = HUGEF; }

                int2 cb = combo[jmin];                 // {row4col, u bits}
                if (cb.x < 0) sink = (int)jmin;
                else { cur_i = cb.x; u_cur = __int_as_float(cb.y); }
            }
            __syncwarp();   // spcfro/path stores visible warp-wide

            // ---- dual v update: vneg[j] += (minVal - spc[j]) for SC columns
            #pragma unroll
            for (int k = 0; k < 5; ++k) {
                #pragma unroll
                for (int h = 0; h < 2; ++h) {
                    int j = 64 * k + lane2 + h;
                    int s = 2 * k + h;
                    if (j < NQ && av[s] == HUGEF)
                        vneg[j] = vneg[j] + (minVal - spcfro[j]);
                }
            }
            // ---- dual u update (reads pre-augmentation col4row)
            if (lane < TT) {
                if (lane == row) u[lane] += minVal;
                else if ((SRmask >> lane) & 1u) u[lane] += minVal - spcfro[col4row[lane]];
            }
            __syncwarp();

            // ---- augment along alternating path (serial, lane 0)
            if (lane == 0) {
                int j = sink;
                for (;;) {
                    int i = path_sh[j];
                    row4col[j] = i;
                    int nj = col4row[i];
                    col4row[i] = j;
                    if (i == row) break;
                    j = nj;
                }
            }
            __syncwarp();
        }

        // boxes_idx = sort(col4row); mark matched set
        if (lane == 0) {
            for (int i = 0; i < TT; ++i) sorted_idx[i] = col4row[i];
            for (int i = 1; i < TT; ++i) {
                int key = sorted_idx[i];
                int k = i - 1;
                while (k >= 0 && sorted_idx[k] > key) { sorted_idx[k + 1] = sorted_idx[k]; --k; }
                sorted_idx[k + 1] = key;
            }
            for (int i = 0; i < TT; ++i) matched[sorted_idx[i]] = 1;
        }
    }
    __syncthreads();

    // ---- BCE over all N queries
    float local = 0.0f;
    for (int n = tid; n < NQ; n += blockDim.x) {
        float p = pc[n];
        float lg = matched[n] ? logf(p) : logf(1.0f - p);
        local += -fmaxf(lg, -100.0f);
    }
    #pragma unroll
    for (int off = 16; off; off >>= 1)
        local += __shfl_down_sync(0xffffffffu, local, off);
    if ((tid & 31) == 0) warpsum[tid >> 5] = local;

    // ---- L1 + GIoU on matched (sorted-index) pairs
    if (tid < TT) {
        int t = tid;
        int n = sorted_idx[t];
        float px = pb[n * 4 + 0], py = pb[n * 4 + 1];
        float pw = pb[n * 4 + 2], ph = pb[n * 4 + 3];
        float tx = tg[t * 4 + 0], ty = tg[t * 4 + 1];
        float tw = tg[t * 4 + 2], th = tg[t * 4 + 3];
        l1s[t] = fabsf(px - tx) + fabsf(py - ty) + fabsf(pw - tw) + fabsf(ph - th);

        float ax0 = px, ay0 = py, ax1 = px + pw, ay1 = py + ph;
        float bx0 = tx, by0 = ty, bx1 = tx + tw, by1 = ty + th;
        float area_a = (ax1 - ax0) * (ay1 - ay0);
        float area_b = (bx1 - bx0) * (by1 - by0);
        float iw = fmaxf(fminf(ax1, bx1) - fmaxf(ax0, bx0), 0.0f);
        float ih = fmaxf(fminf(ay1, by1) - fmaxf(ay0, by0), 0.0f);
        float inter = iw * ih;
        float uni = area_a + area_b - inter;
        float iou = inter / uni;
        float cw = fmaxf(fmaxf(ax1, bx1) - fminf(ax0, bx0), 0.0f);
        float ch = fmaxf(fmaxf(ay1, by1) - fminf(ay0, by0), 0.0f);
        float areac = cw * ch;
        float giou = iou - (areac - uni) / areac;
        gis[t] = 1.0f - giou;
    }
    __syncthreads();

    // ---- per-batch partials + last-block final reduction (deterministic order)
    if (tid == 0) {
        float bce = 0.0f;
        #pragma unroll
        for (int w = 0; w < 8; ++w) bce += warpsum[w];
        float l1 = 0.0f, gi = 0.0f;
        for (int t = 0; t < TT; ++t) { l1 += l1s[t]; gi += gis[t]; }
        g_partials[b * 3 + 0] = bce;
        g_partials[b * 3 + 1] = l1;
        g_partials[b * 3 + 2] = gi;
        __threadfence();
        unsigned ticket = atomicAdd(&g_count, 1u);
        s_last = (ticket == BB - 1) ? 1 : 0;
    }
    __syncthreads();

    if (s_last) {
        __threadfence();
        if (tid < 3) {
            float s = 0.0f;
            for (int bb2 = 0; bb2 < BB; ++bb2) s += g_partials[bb2 * 3 + tid];
            float denom = (tid == 0) ? (float)(BB * NQ) : (float)(BB * TT);
            out[tid] = s / denom;
        }
        if (tid == 0) g_count = 0;   // reset for next graph replay
    }
}

extern "C" void kernel_launch(void* const* d_in, const int* in_sizes, int n_in,
                              void* d_out, int out_size)
{
    const float* pred_boxes = nullptr;
    const float* pred_classes = nullptr;
    const float* targets = nullptr;
    for (int i = 0; i < n_in; ++i) {
        if (in_sizes[i] == BB * NQ * 4)      pred_boxes   = (const float*)d_in[i];
        else if (in_sizes[i] == BB * NQ)     pred_classes = (const float*)d_in[i];
        else if (in_sizes[i] == BB * TT * 4) targets      = (const float*)d_in[i];
    }
    detr_criterion_kernel<<<BB, 256>>>(pred_boxes, pred_classes, targets, (float*)d_out);
}